// round 6
// baseline (speedup 1.0000x reference)
#include <cuda_runtime.h>

// DCN cross layer, L=3, D=1024, B=16384 — algebraic collapse + grouped reduction.
//   a_l = dot(x, W_l); d_ml = dot(bias_m, W_l) (per-CTA constants);
//   alpha recurrence; out = alpha*x + (b0+b1+b2).
// Thread t owns columns [4t,4t+4): W (12 floats) + bsum (4) register-resident,
// ZERO smem W traffic. Rows processed in CTA-wide groups of 4: one barrier per
// 4 rows (double-buffered 12x8 scratch). Next group's x loads are issued
// BEFORE the barrier (barrier wait hides DRAM latency); output phase re-reads
// x (L1-hot, freed registers keep occupancy at 4 CTAs/SM).

static constexpr int D  = 1024;
static constexpr int F4 = D / 4;            // 256
static constexpr int THREADS = 256;
static constexpr int NWARP = THREADS / 32;  // 8
static constexpr int RG = 4;                // rows per reduction group
static constexpr int GROUPS = 4;
static constexpr int ROWS_PER_CTA = RG * GROUPS;   // 16

__device__ __forceinline__ float dot4(float4 a, float4 b) {
    return fmaf(a.x, b.x, fmaf(a.y, b.y, fmaf(a.z, b.z, a.w * b.w)));
}
__device__ __forceinline__ float wred(float v) {
#pragma unroll
    for (int o = 16; o > 0; o >>= 1)
        v += __shfl_xor_sync(0xffffffffu, v, o);
    return v;
}

__global__ __launch_bounds__(THREADS, 4)
void cross_layer_kernel(const float* __restrict__ x,
                        const float* __restrict__ W,
                        const float* __restrict__ bias,
                        float* __restrict__ out)
{
    __shared__ __align__(16) float red[2][12][NWARP];

    const int t    = threadIdx.x;
    const int warp = t >> 5;
    const int lane = t & 31;

    // ---- per-CTA: W/bias to registers, d-constants ----
    const float4* W4 = reinterpret_cast<const float4*>(W);
    const float4* B4 = reinterpret_cast<const float4*>(bias);
    const float4 w0 = W4[t], w1 = W4[F4 + t], w2 = W4[2 * F4 + t];
    const float4 b0 = B4[t], b1 = B4[F4 + t], b2 = B4[2 * F4 + t];
    float4 bsum;
    bsum.x = b0.x + b1.x + b2.x;  bsum.y = b0.y + b1.y + b2.y;
    bsum.z = b0.z + b1.z + b2.z;  bsum.w = b0.w + b1.w + b2.w;

    float p01 = wred(dot4(b0, w1));
    float p2  = wred(dot4(b0, w2) + dot4(b1, w2));     // d02 + d12 combined
    if (lane == 0) { red[0][0][warp] = p01; red[0][1][warp] = p2; }
    __syncthreads();
    float d01 = 0.f, d2 = 0.f;
#pragma unroll
    for (int w = 0; w < NWARP; w++) { d01 += red[0][0][w]; d2 += red[0][1][w]; }
    __syncthreads();                                    // red reused below

    // ---- grouped row loop: 4 rows per barrier ----
    const size_t rowbase = (size_t)blockIdx.x * ROWS_PER_CTA;
    const float4* xp = reinterpret_cast<const float4*>(x) + rowbase * F4 + t;
    float4*       op = reinterpret_cast<float4*>(out)     + rowbase * F4 + t;

    float4 xg[RG];
#pragma unroll
    for (int r = 0; r < RG; r++) xg[r] = xp[(size_t)r * F4];

#pragma unroll
    for (int g = 0; g < GROUPS; g++) {
        const int buf = g & 1;

        // 12 partial dots from registers (no smem W)
        float pr[RG][3];
#pragma unroll
        for (int r = 0; r < RG; r++) {
            pr[r][0] = dot4(xg[r], w0);
            pr[r][1] = dot4(xg[r], w1);
            pr[r][2] = dot4(xg[r], w2);
        }
        // 12 warp reductions + predicated single-lane STS
#pragma unroll
        for (int r = 0; r < RG; r++)
#pragma unroll
            for (int l = 0; l < 3; l++) {
                float v = wred(pr[r][l]);
                if (lane == r * 3 + l) red[buf][r * 3 + l][warp] = v;
            }

        // prefetch next group's x BEFORE the barrier (barrier hides latency)
        if (g + 1 < GROUPS) {
#pragma unroll
            for (int r = 0; r < RG; r++)
                xg[r] = xp[(size_t)((g + 1) * RG + r) * F4];
        }
        __syncthreads();

        // lanes 0..11: sum 8 warp-partials of one reduction (2 LDS.128)
        float S = 0.f;
        if (lane < 12) {
            const float4* rb = reinterpret_cast<const float4*>(&red[buf][lane][0]);
            float4 u0 = rb[0], u1 = rb[1];
            S = ((u0.x + u0.y) + (u0.z + u0.w)) + ((u1.x + u1.y) + (u1.z + u1.w));
        }
        // broadcast the 12 sums, compute 4 alphas (redundant per lane)
        float al[RG];
#pragma unroll
        for (int r = 0; r < RG; r++) {
            float a0 = __shfl_sync(0xffffffffu, S, 3 * r);
            float a1 = __shfl_sync(0xffffffffu, S, 3 * r + 1);
            float a2 = __shfl_sync(0xffffffffu, S, 3 * r + 2);
            float v = 1.f + a0;
            v += fmaf(v, a1, d01);
            v += fmaf(v, a2, d2);
            al[r] = v;
        }

        // output: re-read x (L1-hot), fma, streaming store
#pragma unroll
        for (int r = 0; r < RG; r++) {
            float4 xv = __ldcs(xp + (size_t)(g * RG + r) * F4);
            float4 o;
            o.x = fmaf(al[r], xv.x, bsum.x);
            o.y = fmaf(al[r], xv.y, bsum.y);
            o.z = fmaf(al[r], xv.z, bsum.z);
            o.w = fmaf(al[r], xv.w, bsum.w);
            __stcs(op + (size_t)(g * RG + r) * F4, o);
        }
    }
}

extern "C" void kernel_launch(void* const* d_in, const int* in_sizes, int n_in,
                              void* d_out, int out_size)
{
    const float* x    = (const float*)d_in[0];   // (B, D, 1)
    const float* W    = (const float*)d_in[1];   // (L, D, 1)
    const float* bias = (const float*)d_in[2];   // (L, D, 1)
    float* out = (float*)d_out;

    const int B = in_sizes[0] / D;               // 16384
    cross_layer_kernel<<<B / ROWS_PER_CTA, THREADS>>>(x, W, bias, out);
}